// round 1
// baseline (speedup 1.0000x reference)
#include <cuda_runtime.h>
#include <math.h>
#include <stdint.h>

// Problem constants
constexpr int Bc  = 2;
constexpr int Sc  = 2048;
constexpr int Dc  = 1024;
constexpr int Hc  = 16;
constexpr int HDc = 64;
constexpr int Mc  = Bc * Sc;          // 4096 rows for projections

// ---------------------------------------------------------------------------
// Device scratch (allocations are forbidden; use __device__ globals)
// ---------------------------------------------------------------------------
__device__ float g_q[(size_t)Bc * Sc * Dc];
__device__ float g_k[(size_t)Bc * Sc * Dc];
__device__ float g_v[(size_t)Bc * Sc * Dc];
__device__ float g_ctx[(size_t)Bc * Sc * Dc];

// ---------------------------------------------------------------------------
// SGEMM (NT): C[m,n] = sum_k A[m,k] * B[n,k] + bias[n]
// BM=BN=128, BK=8, 256 threads, 8x8 per thread.
// ---------------------------------------------------------------------------
__global__ __launch_bounds__(256) void sgemm_nt_bias(
    const float* __restrict__ A,     // [M,K]
    const float* __restrict__ B,     // [N,K]
    const float* __restrict__ bias,  // [N]
    float* __restrict__ C,           // [M,N]
    int M, int N, int K)
{
    constexpr int BM = 128, BN = 128, BK = 8;
    constexpr int LDAS = BM + 4;   // padded row stride (floats)
    __shared__ float As[BK][LDAS];
    __shared__ float Bs[BK][LDAS];

    const int tid  = threadIdx.x;
    const int bm   = blockIdx.y * BM;
    const int bn   = blockIdx.x * BN;

    const int lrow = tid >> 1;          // 0..127
    const int lc4  = (tid & 1) * 4;     // 0 or 4

    const int tx = tid & 15;            // 0..15
    const int ty = tid >> 4;            // 0..15

    float acc[8][8];
#pragma unroll
    for (int i = 0; i < 8; i++)
#pragma unroll
        for (int j = 0; j < 8; j++) acc[i][j] = 0.f;

    const float* Aptr = A + (size_t)(bm + lrow) * K + lc4;
    const float* Bptr = B + (size_t)(bn + lrow) * K + lc4;

    for (int k0 = 0; k0 < K; k0 += BK) {
        const float4 av = *(const float4*)(Aptr + k0);
        const float4 bv = *(const float4*)(Bptr + k0);
        __syncthreads();   // previous iteration's reads complete
        As[lc4 + 0][lrow] = av.x;
        As[lc4 + 1][lrow] = av.y;
        As[lc4 + 2][lrow] = av.z;
        As[lc4 + 3][lrow] = av.w;
        Bs[lc4 + 0][lrow] = bv.x;
        Bs[lc4 + 1][lrow] = bv.y;
        Bs[lc4 + 2][lrow] = bv.z;
        Bs[lc4 + 3][lrow] = bv.w;
        __syncthreads();

#pragma unroll
        for (int kk = 0; kk < BK; kk++) {
            float a[8], b[8];
#pragma unroll
            for (int i = 0; i < 8; i++) a[i] = As[kk][ty * 8 + i];
#pragma unroll
            for (int j = 0; j < 8; j++) b[j] = Bs[kk][tx * 8 + j];
#pragma unroll
            for (int i = 0; i < 8; i++)
#pragma unroll
                for (int j = 0; j < 8; j++)
                    acc[i][j] += a[i] * b[j];
        }
    }

#pragma unroll
    for (int i = 0; i < 8; i++) {
        const int row = bm + ty * 8 + i;
#pragma unroll
        for (int j = 0; j < 8; j += 4) {
            const int col = bn + tx * 8 + j;
            float4 o;
            o.x = acc[i][j + 0] + bias[col + 0];
            o.y = acc[i][j + 1] + bias[col + 1];
            o.z = acc[i][j + 2] + bias[col + 2];
            o.w = acc[i][j + 3] + bias[col + 3];
            *(float4*)(C + (size_t)row * N + col) = o;
        }
    }
}

// ---------------------------------------------------------------------------
// Attention: per (b, h, 16-row q tile)
//   scores strip [16,2048] kept in dynamic SMEM -> exact softmax -> weights
//   written to global, then attn @ V streamed.
// Q/K/V live in [B,S,H,HD] layout == [B,S,D] row-major (n = h*HD + d).
// ---------------------------------------------------------------------------
constexpr int TQ = 16;           // q rows per block
constexpr int CH = 64;           // k/v chunk rows
constexpr int SP = Sc + 8;       // padded score row stride (floats)

// dynamic smem layout (floats):
//   sc   : TQ * SP
//   qs   : TQ * 68
//   kv   : CH * 68       (k phase uses stride 65, v phase uses stride 68)
//   redm : TQ * 16
//   reds : TQ * 16
constexpr int SM_SC   = 0;
constexpr int SM_QS   = SM_SC + TQ * SP;
constexpr int SM_KV   = SM_QS + TQ * 68;
constexpr int SM_REDM = SM_KV + CH * 68;
constexpr int SM_REDS = SM_REDM + TQ * 16;
constexpr int SM_TOTAL_FLOATS = SM_REDS + TQ * 16;
constexpr size_t ATTN_SMEM_BYTES = (size_t)SM_TOTAL_FLOATS * sizeof(float);

__global__ __launch_bounds__(256) void attention_kernel(float* __restrict__ attn)
{
    extern __shared__ float sm[];
    float* sc   = sm + SM_SC;
    float* qs   = sm + SM_QS;
    float* kv   = sm + SM_KV;
    float* redm = sm + SM_REDM;
    float* reds = sm + SM_REDS;

    const int tid = threadIdx.x;
    const int qt  = blockIdx.x;   // 0..S/TQ-1
    const int h   = blockIdx.y;   // 0..H-1
    const int b   = blockIdx.z;   // 0..B-1

    const float* Qb = g_q + (size_t)b * Sc * Dc + h * HDc;
    const float* Kb = g_k + (size_t)b * Sc * Dc + h * HDc;
    const float* Vb = g_v + (size_t)b * Sc * Dc + h * HDc;

    // ---- load q tile [TQ, 64] (stride 68 in smem) ----
    {
        const int r  = tid >> 4;          // 0..15
        const int c4 = (tid & 15) * 4;    // 0..60
        const float4 v = *(const float4*)(Qb + (size_t)(qt * TQ + r) * Dc + c4);
        qs[r * 68 + c4 + 0] = v.x;
        qs[r * 68 + c4 + 1] = v.y;
        qs[r * 68 + c4 + 2] = v.z;
        qs[r * 68 + c4 + 3] = v.w;
    }
    __syncthreads();

    // ---- phase 1: scores (stride-65 k layout) ----
    {
        const int i  = tid >> 4;          // q row
        const int j0 = (tid & 15) * 4;    // key col base within chunk
        const float* qrow = qs + i * 68;

        for (int c = 0; c < Sc / CH; c++) {
#pragma unroll
            for (int it = 0; it < 4; it++) {
                const int idx = tid + it * 256;       // 0..1023
                const int r   = idx >> 4;             // 0..63
                const int c4  = (idx & 15) * 4;       // 0..60
                const float4 v = *(const float4*)(Kb + (size_t)(c * CH + r) * Dc + c4);
                kv[r * 65 + c4 + 0] = v.x;
                kv[r * 65 + c4 + 1] = v.y;
                kv[r * 65 + c4 + 2] = v.z;
                kv[r * 65 + c4 + 3] = v.w;
            }
            __syncthreads();

            float a0 = 0.f, a1 = 0.f, a2 = 0.f, a3 = 0.f;
            const float* k0p = kv + (j0 + 0) * 65;
            const float* k1p = kv + (j0 + 1) * 65;
            const float* k2p = kv + (j0 + 2) * 65;
            const float* k3p = kv + (j0 + 3) * 65;
#pragma unroll 16
            for (int d = 0; d < HDc; d++) {
                const float qv = qrow[d];
                a0 += qv * k0p[d];
                a1 += qv * k1p[d];
                a2 += qv * k2p[d];
                a3 += qv * k3p[d];
            }
            float* srow = sc + i * SP + c * CH + j0;
            srow[0] = a0 * 0.125f;
            srow[1] = a1 * 0.125f;
            srow[2] = a2 * 0.125f;
            srow[3] = a3 * 0.125f;
            __syncthreads();   // before overwriting kv next chunk
        }
    }

    // ---- phase 2: softmax over each 2048-row ----
    {
        const int i    = tid >> 4;
        const int lane = tid & 15;
        float* row = sc + i * SP;

        float m = -INFINITY;
        for (int j = lane; j < Sc; j += 16) m = fmaxf(m, row[j]);
        redm[i * 16 + lane] = m;
        __syncthreads();
        m = redm[i * 16];
#pragma unroll
        for (int l = 1; l < 16; l++) m = fmaxf(m, redm[i * 16 + l]);

        float s = 0.f;
        for (int j = lane; j < Sc; j += 16) {
            const float e = __expf(row[j] - m);
            row[j] = e;
            s += e;
        }
        reds[i * 16 + lane] = s;
        __syncthreads();
        s = reds[i * 16];
#pragma unroll
        for (int l = 1; l < 16; l++) s += reds[i * 16 + l];
        const float inv = 1.0f / s;
        for (int j = lane; j < Sc; j += 16) row[j] *= inv;
    }
    __syncthreads();

    // ---- write attention weights, fully coalesced float4 stores ----
    {
        float* aw = attn + (((size_t)(b * Hc + h) * Sc + (size_t)qt * TQ) * Sc);
#pragma unroll
        for (int ii = 0; ii < TQ; ii++) {
            const float* r2 = sc + ii * SP;
            float* dst = aw + (size_t)ii * Sc;
            for (int j4 = tid * 4; j4 < Sc; j4 += 1024) {
                float4 v;
                v.x = r2[j4 + 0];
                v.y = r2[j4 + 1];
                v.z = r2[j4 + 2];
                v.w = r2[j4 + 3];
                *(float4*)(dst + j4) = v;
            }
        }
    }

    // ---- phase 3: out = P @ V (stride-68 v layout, float4 over d) ----
    {
        const int i  = tid >> 4;
        const int d0 = (tid & 15) * 4;
        float4 acc = make_float4(0.f, 0.f, 0.f, 0.f);

        for (int c = 0; c < Sc / CH; c++) {
            __syncthreads();   // previous chunk's reads complete (also orders vs attn writes: no-op)
#pragma unroll
            for (int it = 0; it < 4; it++) {
                const int idx = tid + it * 256;
                const int r   = idx >> 4;
                const int c4  = (idx & 15) * 4;
                const float4 v = *(const float4*)(Vb + (size_t)(c * CH + r) * Dc + c4);
                *(float4*)(kv + r * 68 + c4) = v;
            }
            __syncthreads();

            const float* prow = sc + i * SP + c * CH;
#pragma unroll 16
            for (int j = 0; j < CH; j++) {
                const float p = prow[j];
                const float4 vv = *(const float4*)(kv + j * 68 + d0);
                acc.x += p * vv.x;
                acc.y += p * vv.y;
                acc.z += p * vv.z;
                acc.w += p * vv.w;
            }
        }

        float* dst = g_ctx + (size_t)(b * Sc + qt * TQ + i) * Dc + h * HDc + d0;
        *(float4*)dst = acc;
    }
}

// ---------------------------------------------------------------------------
// kernel_launch
//   d_in: x, Wq, bq, Wk, bk, Wv, bv, Wo, bo   (all fp32)
//   d_out: [ out (B*S*D) | attention_weights (B*H*S*S) ]  fp32
// ---------------------------------------------------------------------------
extern "C" void kernel_launch(void* const* d_in, const int* in_sizes, int n_in,
                              void* d_out, int out_size)
{
    (void)in_sizes; (void)n_in; (void)out_size;
    const float* x  = (const float*)d_in[0];
    const float* Wq = (const float*)d_in[1];
    const float* bq = (const float*)d_in[2];
    const float* Wk = (const float*)d_in[3];
    const float* bk = (const float*)d_in[4];
    const float* Wv = (const float*)d_in[5];
    const float* bv = (const float*)d_in[6];
    const float* Wo = (const float*)d_in[7];
    const float* bo = (const float*)d_in[8];

    float* out  = (float*)d_out;
    float* attn = out + (size_t)Bc * Sc * Dc;

    float* gq;  cudaGetSymbolAddress((void**)&gq,  g_q);
    float* gk;  cudaGetSymbolAddress((void**)&gk,  g_k);
    float* gv;  cudaGetSymbolAddress((void**)&gv,  g_v);
    float* gc;  cudaGetSymbolAddress((void**)&gc,  g_ctx);

    cudaFuncSetAttribute(attention_kernel,
                         cudaFuncAttributeMaxDynamicSharedMemorySize,
                         (int)ATTN_SMEM_BYTES);

    dim3 gemmGrid(Dc / 128, Mc / 128);   // (8, 32)
    dim3 gemmBlock(256);

    // Q/K/V projections
    sgemm_nt_bias<<<gemmGrid, gemmBlock>>>(x, Wq, bq, gq, Mc, Dc, Dc);
    sgemm_nt_bias<<<gemmGrid, gemmBlock>>>(x, Wk, bk, gk, Mc, Dc, Dc);
    sgemm_nt_bias<<<gemmGrid, gemmBlock>>>(x, Wv, bv, gv, Mc, Dc, Dc);

    // Attention + weight output + ctx
    dim3 attnGrid(Sc / TQ, Hc, Bc);      // (128, 16, 2)
    attention_kernel<<<attnGrid, 256, ATTN_SMEM_BYTES>>>(attn);

    // Output projection
    sgemm_nt_bias<<<gemmGrid, gemmBlock>>>(gc, Wo, bo, out, Mc, Dc, Dc);
}

// round 2
// speedup vs baseline: 4.0170x; 4.0170x over previous
#include <cuda_runtime.h>
#include <math.h>
#include <stdint.h>

// Problem constants
constexpr int Bc  = 2;
constexpr int Sc  = 2048;
constexpr int Dc  = 1024;
constexpr int Hc  = 16;
constexpr int HDc = 64;
constexpr int Mc  = Bc * Sc;          // 4096 rows for projections

// ---------------------------------------------------------------------------
// Device scratch (allocations forbidden; use __device__ globals)
// ---------------------------------------------------------------------------
__device__ float g_q[(size_t)Bc * Sc * Dc];
__device__ float g_k[(size_t)Bc * Sc * Dc];
__device__ float g_v[(size_t)Bc * Sc * Dc];
__device__ float g_ctx[(size_t)Bc * Sc * Dc];

// ---------------------------------------------------------------------------
// Helpers
// ---------------------------------------------------------------------------
__device__ __forceinline__ uint32_t f2tf32(float f) {
    uint32_t u;
    asm("cvt.rna.tf32.f32 %0, %1;" : "=r"(u) : "f"(f));
    return u;
}
__device__ __forceinline__ float f2tf32f(float f) {
    return __uint_as_float(f2tf32(f));
}

// D += A(16x8, tf32) * B(8x8, tf32)   (m16n8k8, row.col)
__device__ __forceinline__ void mma_tf32(float* d, const uint32_t* a, const uint32_t* b) {
    asm volatile(
        "mma.sync.aligned.m16n8k8.row.col.f32.tf32.tf32.f32 "
        "{%0,%1,%2,%3}, {%4,%5,%6,%7}, {%8,%9}, {%0,%1,%2,%3};"
        : "+f"(d[0]), "+f"(d[1]), "+f"(d[2]), "+f"(d[3])
        : "r"(a[0]), "r"(a[1]), "r"(a[2]), "r"(a[3]), "r"(b[0]), "r"(b[1]));
}

// ---------------------------------------------------------------------------
// tf32 GEMM (NT): C[m,n] = sum_k A[m,k] * B[n,k] + bias[n]
// BM=128, BN=64, BK=32, 256 threads = 8 warps (4m x 2n), warp tile 32x32.
// ---------------------------------------------------------------------------
__global__ __launch_bounds__(256) void gemm_tf32_nt_bias(
    const float* __restrict__ A,     // [M,K]
    const float* __restrict__ B,     // [N,K]
    const float* __restrict__ bias,  // [N]
    float* __restrict__ C,           // [M,N]
    int M, int N, int K)
{
    __shared__ float As[128][36];
    __shared__ float Bs[64][36];

    const int tid  = threadIdx.x;
    const int lane = tid & 31;
    const int warp = tid >> 5;
    const int wm   = warp >> 1;          // 0..3
    const int wn   = warp & 1;           // 0..1
    const int g    = lane >> 2;          // 0..7
    const int t    = lane & 3;           // 0..3
    const int bm   = blockIdx.y * 128;
    const int bn   = blockIdx.x * 64;

    float acc[2][4][4];
#pragma unroll
    for (int mt = 0; mt < 2; mt++)
#pragma unroll
        for (int nt = 0; nt < 4; nt++)
#pragma unroll
            for (int i = 0; i < 4; i++) acc[mt][nt][i] = 0.f;

    float4 aReg[4], bReg[2];

    // prefetch k0 = 0
#pragma unroll
    for (int i = 0; i < 4; i++) {
        const int f   = tid + i * 256;
        const int row = f >> 3;
        const int c4  = (f & 7) * 4;
        aReg[i] = *(const float4*)(A + (size_t)(bm + row) * K + c4);
    }
#pragma unroll
    for (int i = 0; i < 2; i++) {
        const int f   = tid + i * 256;
        const int row = f >> 3;
        const int c4  = (f & 7) * 4;
        bReg[i] = *(const float4*)(B + (size_t)(bn + row) * K + c4);
    }

    for (int k0 = 0; k0 < K; k0 += 32) {
        __syncthreads();   // previous compute done with smem
#pragma unroll
        for (int i = 0; i < 4; i++) {
            const int f   = tid + i * 256;
            const int row = f >> 3;
            const int c4  = (f & 7) * 4;
            As[row][c4 + 0] = f2tf32f(aReg[i].x);
            As[row][c4 + 1] = f2tf32f(aReg[i].y);
            As[row][c4 + 2] = f2tf32f(aReg[i].z);
            As[row][c4 + 3] = f2tf32f(aReg[i].w);
        }
#pragma unroll
        for (int i = 0; i < 2; i++) {
            const int f   = tid + i * 256;
            const int row = f >> 3;
            const int c4  = (f & 7) * 4;
            Bs[row][c4 + 0] = f2tf32f(bReg[i].x);
            Bs[row][c4 + 1] = f2tf32f(bReg[i].y);
            Bs[row][c4 + 2] = f2tf32f(bReg[i].z);
            Bs[row][c4 + 3] = f2tf32f(bReg[i].w);
        }
        __syncthreads();

        if (k0 + 32 < K) {
#pragma unroll
            for (int i = 0; i < 4; i++) {
                const int f   = tid + i * 256;
                const int row = f >> 3;
                const int c4  = (f & 7) * 4;
                aReg[i] = *(const float4*)(A + (size_t)(bm + row) * K + k0 + 32 + c4);
            }
#pragma unroll
            for (int i = 0; i < 2; i++) {
                const int f   = tid + i * 256;
                const int row = f >> 3;
                const int c4  = (f & 7) * 4;
                bReg[i] = *(const float4*)(B + (size_t)(bn + row) * K + k0 + 32 + c4);
            }
        }

#pragma unroll
        for (int ks = 0; ks < 4; ks++) {
            uint32_t af[2][4], bf[4][2];
#pragma unroll
            for (int mt = 0; mt < 2; mt++) {
                const int r = wm * 32 + mt * 16 + g;
                af[mt][0] = __float_as_uint(As[r    ][ks * 8 + t    ]);
                af[mt][1] = __float_as_uint(As[r + 8][ks * 8 + t    ]);
                af[mt][2] = __float_as_uint(As[r    ][ks * 8 + t + 4]);
                af[mt][3] = __float_as_uint(As[r + 8][ks * 8 + t + 4]);
            }
#pragma unroll
            for (int nt = 0; nt < 4; nt++) {
                const int c = wn * 32 + nt * 8 + g;
                bf[nt][0] = __float_as_uint(Bs[c][ks * 8 + t    ]);
                bf[nt][1] = __float_as_uint(Bs[c][ks * 8 + t + 4]);
            }
#pragma unroll
            for (int mt = 0; mt < 2; mt++)
#pragma unroll
                for (int nt = 0; nt < 4; nt++)
                    mma_tf32(acc[mt][nt], af[mt], bf[nt]);
        }
    }

    // epilogue
#pragma unroll
    for (int mt = 0; mt < 2; mt++) {
#pragma unroll
        for (int nt = 0; nt < 4; nt++) {
            const int row = bm + wm * 32 + mt * 16 + g;
            const int col = bn + wn * 32 + nt * 8 + 2 * t;
            const float2 bv = *(const float2*)(bias + col);
            float2 o0, o1;
            o0.x = acc[mt][nt][0] + bv.x;
            o0.y = acc[mt][nt][1] + bv.y;
            o1.x = acc[mt][nt][2] + bv.x;
            o1.y = acc[mt][nt][3] + bv.y;
            *(float2*)(C + (size_t)row * N + col)       = o0;
            *(float2*)(C + (size_t)(row + 8) * N + col) = o1;
        }
    }
}

// ---------------------------------------------------------------------------
// Attention (tensor-core, two-pass exact softmax with recompute):
//   block = (qt: 64 q rows, h, b), 128 threads = 4 warps, warp owns 16 q rows.
//   pass 1: S = Q@K^T tile-by-tile (tf32 mma), online row max m and sum Z.
//   pass 2: recompute S (bit-identical), P = exp(S-m)/Z, write weights
//           coalesced, accumulate ctx = P@V (tf32 mma).
// ---------------------------------------------------------------------------
constexpr int AT_Q    = 64;                        // q rows per block
constexpr int AT_LD   = 68;                        // smem row stride (floats)
constexpr int SM_QS   = 0;                         // Qs [64][68]
constexpr int SM_KVS  = SM_QS + AT_Q * AT_LD;      // K/V tile [64][68]
constexpr int SM_PS   = SM_KVS + 64 * AT_LD;       // P tile [64][68] (fp32)
constexpr int ATT_SMEM_FLOATS = SM_PS + AT_Q * AT_LD;
constexpr size_t ATT_SMEM_BYTES = (size_t)ATT_SMEM_FLOATS * sizeof(float);

__global__ __launch_bounds__(128) void attention_tc_kernel(float* __restrict__ attn)
{
    extern __shared__ float sm[];
    float* Qs  = sm + SM_QS;
    float* KVs = sm + SM_KVS;
    float* Ps  = sm + SM_PS;

    const int tid  = threadIdx.x;
    const int lane = tid & 31;
    const int warp = tid >> 5;           // 0..3
    const int g    = lane >> 2;          // 0..7
    const int t    = lane & 3;           // 0..3

    const int qt = blockIdx.x;           // 0..31
    const int h  = blockIdx.y;
    const int b  = blockIdx.z;

    const float* Qg = g_q + (size_t)b * Sc * Dc + h * HDc;
    const float* Kg = g_k + (size_t)b * Sc * Dc + h * HDc;
    const float* Vg = g_v + (size_t)b * Sc * Dc + h * HDc;

    // ---- load Q tile [64, 64], scaled by 1/sqrt(HD), tf32-rounded ----
#pragma unroll
    for (int i = 0; i < 8; i++) {
        const int f   = tid + i * 128;
        const int r   = f >> 4;
        const int c4  = (f & 15) * 4;
        float4 v = *(const float4*)(Qg + (size_t)(qt * AT_Q + r) * Dc + c4);
        Qs[r * AT_LD + c4 + 0] = f2tf32f(v.x * 0.125f);
        Qs[r * AT_LD + c4 + 1] = f2tf32f(v.y * 0.125f);
        Qs[r * AT_LD + c4 + 2] = f2tf32f(v.z * 0.125f);
        Qs[r * AT_LD + c4 + 3] = f2tf32f(v.w * 0.125f);
    }
    __syncthreads();

    // per-thread row stats (rows: warp*16 + g and +8)
    float m0 = -INFINITY, m1 = -INFINITY, Z0 = 0.f, Z1 = 0.f;

    // ================= PASS 1: online max / sum =================
    for (int kt = 0; kt < Sc / 64; kt++) {
        // load K tile [64,64] tf32-rounded
#pragma unroll
        for (int i = 0; i < 8; i++) {
            const int f  = tid + i * 128;
            const int r  = f >> 4;
            const int c4 = (f & 15) * 4;
            float4 v = *(const float4*)(Kg + (size_t)(kt * 64 + r) * Dc + c4);
            KVs[r * AT_LD + c4 + 0] = f2tf32f(v.x);
            KVs[r * AT_LD + c4 + 1] = f2tf32f(v.y);
            KVs[r * AT_LD + c4 + 2] = f2tf32f(v.z);
            KVs[r * AT_LD + c4 + 3] = f2tf32f(v.w);
        }
        __syncthreads();

        float sacc[8][4];
#pragma unroll
        for (int nt = 0; nt < 8; nt++)
#pragma unroll
            for (int i = 0; i < 4; i++) sacc[nt][i] = 0.f;

#pragma unroll
        for (int ks = 0; ks < 8; ks++) {
            uint32_t af[4];
            const int qr = warp * 16 + g;
            af[0] = __float_as_uint(Qs[(qr    ) * AT_LD + ks * 8 + t    ]);
            af[1] = __float_as_uint(Qs[(qr + 8) * AT_LD + ks * 8 + t    ]);
            af[2] = __float_as_uint(Qs[(qr    ) * AT_LD + ks * 8 + t + 4]);
            af[3] = __float_as_uint(Qs[(qr + 8) * AT_LD + ks * 8 + t + 4]);
#pragma unroll
            for (int nt = 0; nt < 8; nt++) {
                uint32_t bf[2];
                bf[0] = __float_as_uint(KVs[(nt * 8 + g) * AT_LD + ks * 8 + t    ]);
                bf[1] = __float_as_uint(KVs[(nt * 8 + g) * AT_LD + ks * 8 + t + 4]);
                mma_tf32(sacc[nt], af, bf);
            }
        }

        // tile max per row
        float tm0 = -INFINITY, tm1 = -INFINITY;
#pragma unroll
        for (int nt = 0; nt < 8; nt++) {
            tm0 = fmaxf(tm0, fmaxf(sacc[nt][0], sacc[nt][1]));
            tm1 = fmaxf(tm1, fmaxf(sacc[nt][2], sacc[nt][3]));
        }
        tm0 = fmaxf(tm0, __shfl_xor_sync(0xffffffff, tm0, 1));
        tm0 = fmaxf(tm0, __shfl_xor_sync(0xffffffff, tm0, 2));
        tm1 = fmaxf(tm1, __shfl_xor_sync(0xffffffff, tm1, 1));
        tm1 = fmaxf(tm1, __shfl_xor_sync(0xffffffff, tm1, 2));

        const float m0n = fmaxf(m0, tm0);
        const float m1n = fmaxf(m1, tm1);

        float s0 = 0.f, s1 = 0.f;
#pragma unroll
        for (int nt = 0; nt < 8; nt++) {
            s0 += __expf(sacc[nt][0] - m0n) + __expf(sacc[nt][1] - m0n);
            s1 += __expf(sacc[nt][2] - m1n) + __expf(sacc[nt][3] - m1n);
        }
        s0 += __shfl_xor_sync(0xffffffff, s0, 1);
        s0 += __shfl_xor_sync(0xffffffff, s0, 2);
        s1 += __shfl_xor_sync(0xffffffff, s1, 1);
        s1 += __shfl_xor_sync(0xffffffff, s1, 2);

        Z0 = Z0 * __expf(m0 - m0n) + s0;  m0 = m0n;
        Z1 = Z1 * __expf(m1 - m1n) + s1;  m1 = m1n;

        __syncthreads();   // before overwriting KVs
    }

    const float invZ0 = 1.0f / Z0;
    const float invZ1 = 1.0f / Z1;

    // ================= PASS 2: weights + P@V =================
    float ctx[8][4];
#pragma unroll
    for (int nt = 0; nt < 8; nt++)
#pragma unroll
        for (int i = 0; i < 4; i++) ctx[nt][i] = 0.f;

    float* aw = attn + (((size_t)(b * Hc + h) * Sc + (size_t)qt * AT_Q) * Sc);

    for (int kt = 0; kt < Sc / 64; kt++) {
        // reload K tile (bit-identical scores)
#pragma unroll
        for (int i = 0; i < 8; i++) {
            const int f  = tid + i * 128;
            const int r  = f >> 4;
            const int c4 = (f & 15) * 4;
            float4 v = *(const float4*)(Kg + (size_t)(kt * 64 + r) * Dc + c4);
            KVs[r * AT_LD + c4 + 0] = f2tf32f(v.x);
            KVs[r * AT_LD + c4 + 1] = f2tf32f(v.y);
            KVs[r * AT_LD + c4 + 2] = f2tf32f(v.z);
            KVs[r * AT_LD + c4 + 3] = f2tf32f(v.w);
        }
        __syncthreads();

        float sacc[8][4];
#pragma unroll
        for (int nt = 0; nt < 8; nt++)
#pragma unroll
            for (int i = 0; i < 4; i++) sacc[nt][i] = 0.f;

#pragma unroll
        for (int ks = 0; ks < 8; ks++) {
            uint32_t af[4];
            const int qr = warp * 16 + g;
            af[0] = __float_as_uint(Qs[(qr    ) * AT_LD + ks * 8 + t    ]);
            af[1] = __float_as_uint(Qs[(qr + 8) * AT_LD + ks * 8 + t    ]);
            af[2] = __float_as_uint(Qs[(qr    ) * AT_LD + ks * 8 + t + 4]);
            af[3] = __float_as_uint(Qs[(qr + 8) * AT_LD + ks * 8 + t + 4]);
#pragma unroll
            for (int nt = 0; nt < 8; nt++) {
                uint32_t bf[2];
                bf[0] = __float_as_uint(KVs[(nt * 8 + g) * AT_LD + ks * 8 + t    ]);
                bf[1] = __float_as_uint(KVs[(nt * 8 + g) * AT_LD + ks * 8 + t + 4]);
                mma_tf32(sacc[nt], af, bf);
            }
        }

        // P = exp(s - m) / Z  -> stage in smem (fp32)
        const int pr = warp * 16 + g;
#pragma unroll
        for (int nt = 0; nt < 8; nt++) {
            const float p00 = __expf(sacc[nt][0] - m0) * invZ0;
            const float p01 = __expf(sacc[nt][1] - m0) * invZ0;
            const float p10 = __expf(sacc[nt][2] - m1) * invZ1;
            const float p11 = __expf(sacc[nt][3] - m1) * invZ1;
            Ps[(pr    ) * AT_LD + nt * 8 + 2 * t    ] = p00;
            Ps[(pr    ) * AT_LD + nt * 8 + 2 * t + 1] = p01;
            Ps[(pr + 8) * AT_LD + nt * 8 + 2 * t    ] = p10;
            Ps[(pr + 8) * AT_LD + nt * 8 + 2 * t + 1] = p11;
        }
        __syncthreads();

        // write attention weights (coalesced float4) + load V tile
#pragma unroll
        for (int i = 0; i < 8; i++) {
            const int f  = tid + i * 128;
            const int r  = f >> 4;
            const int c4 = (f & 15) * 4;
            const float4 pv = *(const float4*)(Ps + r * AT_LD + c4);
            *(float4*)(aw + (size_t)r * Sc + kt * 64 + c4) = pv;
            float4 v = *(const float4*)(Vg + (size_t)(kt * 64 + r) * Dc + c4);
            KVs[r * AT_LD + c4 + 0] = f2tf32f(v.x);
            KVs[r * AT_LD + c4 + 1] = f2tf32f(v.y);
            KVs[r * AT_LD + c4 + 2] = f2tf32f(v.z);
            KVs[r * AT_LD + c4 + 3] = f2tf32f(v.w);
        }
        __syncthreads();

        // ctx += P @ V
#pragma unroll
        for (int ks = 0; ks < 8; ks++) {
            uint32_t af[4];
            af[0] = f2tf32(Ps[(pr    ) * AT_LD + ks * 8 + t    ]);
            af[1] = f2tf32(Ps[(pr + 8) * AT_LD + ks * 8 + t    ]);
            af[2] = f2tf32(Ps[(pr    ) * AT_LD + ks * 8 + t + 4]);
            af[3] = f2tf32(Ps[(pr + 8) * AT_LD + ks * 8 + t + 4]);
#pragma unroll
            for (int nt = 0; nt < 8; nt++) {
                uint32_t bf[2];
                bf[0] = __float_as_uint(KVs[(ks * 8 + t    ) * AT_LD + nt * 8 + g]);
                bf[1] = __float_as_uint(KVs[(ks * 8 + t + 4) * AT_LD + nt * 8 + g]);
                mma_tf32(ctx[nt], af, bf);
            }
        }
        __syncthreads();   // before next K tile overwrites KVs
    }

    // ---- write ctx [64, 64] to g_ctx (merged-head layout) ----
    {
        const int r = warp * 16 + g;
#pragma unroll
        for (int nt = 0; nt < 8; nt++) {
            const int col = h * HDc + nt * 8 + 2 * t;
            float2 o0, o1;
            o0.x = ctx[nt][0]; o0.y = ctx[nt][1];
            o1.x = ctx[nt][2]; o1.y = ctx[nt][3];
            *(float2*)(g_ctx + (size_t)(b * Sc + qt * AT_Q + r    ) * Dc + col) = o0;
            *(float2*)(g_ctx + (size_t)(b * Sc + qt * AT_Q + r + 8) * Dc + col) = o1;
        }
    }
}

// ---------------------------------------------------------------------------
// kernel_launch
//   d_in: x, Wq, bq, Wk, bk, Wv, bv, Wo, bo   (all fp32)
//   d_out: [ out (B*S*D) | attention_weights (B*H*S*S) ]  fp32
// ---------------------------------------------------------------------------
extern "C" void kernel_launch(void* const* d_in, const int* in_sizes, int n_in,
                              void* d_out, int out_size)
{
    (void)in_sizes; (void)n_in; (void)out_size;
    const float* x  = (const float*)d_in[0];
    const float* Wq = (const float*)d_in[1];
    const float* bq = (const float*)d_in[2];
    const float* Wk = (const float*)d_in[3];
    const float* bk = (const float*)d_in[4];
    const float* Wv = (const float*)d_in[5];
    const float* bv = (const float*)d_in[6];
    const float* Wo = (const float*)d_in[7];
    const float* bo = (const float*)d_in[8];

    float* out  = (float*)d_out;
    float* attn = out + (size_t)Bc * Sc * Dc;

    float* gq;  cudaGetSymbolAddress((void**)&gq,  g_q);
    float* gk;  cudaGetSymbolAddress((void**)&gk,  g_k);
    float* gv;  cudaGetSymbolAddress((void**)&gv,  g_v);
    float* gc;  cudaGetSymbolAddress((void**)&gc,  g_ctx);

    cudaFuncSetAttribute(attention_tc_kernel,
                         cudaFuncAttributeMaxDynamicSharedMemorySize,
                         (int)ATT_SMEM_BYTES);

    dim3 gemmGrid(Dc / 64, Mc / 128);   // (16, 32)
    dim3 gemmBlock(256);

    // Q/K/V projections
    gemm_tf32_nt_bias<<<gemmGrid, gemmBlock>>>(x, Wq, bq, gq, Mc, Dc, Dc);
    gemm_tf32_nt_bias<<<gemmGrid, gemmBlock>>>(x, Wk, bk, gk, Mc, Dc, Dc);
    gemm_tf32_nt_bias<<<gemmGrid, gemmBlock>>>(x, Wv, bv, gv, Mc, Dc, Dc);

    // Attention: weights + ctx
    dim3 attnGrid(Sc / AT_Q, Hc, Bc);   // (32, 16, 2)
    attention_tc_kernel<<<attnGrid, 128, ATT_SMEM_BYTES>>>(attn);

    // Output projection
    gemm_tf32_nt_bias<<<gemmGrid, gemmBlock>>>(gc, Wo, bo, out, Mc, Dc, Dc);
}

// round 3
// speedup vs baseline: 5.0393x; 1.2545x over previous
#include <cuda_runtime.h>
#include <math.h>
#include <stdint.h>

// Problem constants
constexpr int Bc  = 2;
constexpr int Sc  = 2048;
constexpr int Dc  = 1024;
constexpr int Hc  = 16;
constexpr int HDc = 64;
constexpr int Mc  = Bc * Sc;          // 4096 rows for projections

// ---------------------------------------------------------------------------
// Device scratch (allocations forbidden; use __device__ globals)
// ---------------------------------------------------------------------------
__device__ float g_q[(size_t)Bc * Sc * Dc];
__device__ float g_k[(size_t)Bc * Sc * Dc];
__device__ float g_v[(size_t)Bc * Sc * Dc];
__device__ float g_ctx[(size_t)Bc * Sc * Dc];
__device__ float g_m[(size_t)Bc * Hc * Sc];   // per-row softmax max
__device__ float g_z[(size_t)Bc * Hc * Sc];   // per-row softmax sum

// ---------------------------------------------------------------------------
// Helpers
// ---------------------------------------------------------------------------
__device__ __forceinline__ uint32_t f2tf32(float f) {
    uint32_t u;
    asm("cvt.rna.tf32.f32 %0, %1;" : "=r"(u) : "f"(f));
    return u;
}
__device__ __forceinline__ float f2tf32f(float f) {
    return __uint_as_float(f2tf32(f));
}

// D += A(16x8, tf32) * B(8x8, tf32)   (m16n8k8, row.col)
__device__ __forceinline__ void mma_tf32(float* d, const uint32_t* a, const uint32_t* b) {
    asm volatile(
        "mma.sync.aligned.m16n8k8.row.col.f32.tf32.tf32.f32 "
        "{%0,%1,%2,%3}, {%4,%5,%6,%7}, {%8,%9}, {%0,%1,%2,%3};"
        : "+f"(d[0]), "+f"(d[1]), "+f"(d[2]), "+f"(d[3])
        : "r"(a[0]), "r"(a[1]), "r"(a[2]), "r"(a[3]), "r"(b[0]), "r"(b[1]));
}

// ---------------------------------------------------------------------------
// tf32 GEMM (NT), 3 problems fused via blockIdx.z:
//   Cz[m,n] = sum_k A[m,k] * Wz[n,k] + bz[n]
// BM=128, BN=64, BK=32, 256 threads = 8 warps (4m x 2n), warp tile 32x32.
// ---------------------------------------------------------------------------
__global__ __launch_bounds__(256) void gemm3_tf32_nt_bias(
    const float* __restrict__ A,
    const float* __restrict__ W0, const float* __restrict__ b0, float* __restrict__ C0,
    const float* __restrict__ W1, const float* __restrict__ b1, float* __restrict__ C1,
    const float* __restrict__ W2, const float* __restrict__ b2, float* __restrict__ C2,
    int M, int N, int K)
{
    const int z = blockIdx.z;
    const float* B    = (z == 0) ? W0 : (z == 1) ? W1 : W2;
    const float* bias = (z == 0) ? b0 : (z == 1) ? b1 : b2;
    float*       C    = (z == 0) ? C0 : (z == 1) ? C1 : C2;

    __shared__ float As[128][36];
    __shared__ float Bs[64][36];

    const int tid  = threadIdx.x;
    const int lane = tid & 31;
    const int warp = tid >> 5;
    const int wm   = warp >> 1;          // 0..3
    const int wn   = warp & 1;           // 0..1
    const int g    = lane >> 2;          // 0..7
    const int t    = lane & 3;           // 0..3
    const int bm   = blockIdx.y * 128;
    const int bn   = blockIdx.x * 64;

    float acc[2][4][4];
#pragma unroll
    for (int mt = 0; mt < 2; mt++)
#pragma unroll
        for (int nt = 0; nt < 4; nt++)
#pragma unroll
            for (int i = 0; i < 4; i++) acc[mt][nt][i] = 0.f;

    float4 aReg[4], bReg[2];

#pragma unroll
    for (int i = 0; i < 4; i++) {
        const int f   = tid + i * 256;
        const int row = f >> 3;
        const int c4  = (f & 7) * 4;
        aReg[i] = *(const float4*)(A + (size_t)(bm + row) * K + c4);
    }
#pragma unroll
    for (int i = 0; i < 2; i++) {
        const int f   = tid + i * 256;
        const int row = f >> 3;
        const int c4  = (f & 7) * 4;
        bReg[i] = *(const float4*)(B + (size_t)(bn + row) * K + c4);
    }

    for (int k0 = 0; k0 < K; k0 += 32) {
        __syncthreads();
#pragma unroll
        for (int i = 0; i < 4; i++) {
            const int f   = tid + i * 256;
            const int row = f >> 3;
            const int c4  = (f & 7) * 4;
            As[row][c4 + 0] = f2tf32f(aReg[i].x);
            As[row][c4 + 1] = f2tf32f(aReg[i].y);
            As[row][c4 + 2] = f2tf32f(aReg[i].z);
            As[row][c4 + 3] = f2tf32f(aReg[i].w);
        }
#pragma unroll
        for (int i = 0; i < 2; i++) {
            const int f   = tid + i * 256;
            const int row = f >> 3;
            const int c4  = (f & 7) * 4;
            Bs[row][c4 + 0] = f2tf32f(bReg[i].x);
            Bs[row][c4 + 1] = f2tf32f(bReg[i].y);
            Bs[row][c4 + 2] = f2tf32f(bReg[i].z);
            Bs[row][c4 + 3] = f2tf32f(bReg[i].w);
        }
        __syncthreads();

        if (k0 + 32 < K) {
#pragma unroll
            for (int i = 0; i < 4; i++) {
                const int f   = tid + i * 256;
                const int row = f >> 3;
                const int c4  = (f & 7) * 4;
                aReg[i] = *(const float4*)(A + (size_t)(bm + row) * K + k0 + 32 + c4);
            }
#pragma unroll
            for (int i = 0; i < 2; i++) {
                const int f   = tid + i * 256;
                const int row = f >> 3;
                const int c4  = (f & 7) * 4;
                bReg[i] = *(const float4*)(B + (size_t)(bn + row) * K + k0 + 32 + c4);
            }
        }

#pragma unroll
        for (int ks = 0; ks < 4; ks++) {
            uint32_t af[2][4], bf[4][2];
#pragma unroll
            for (int mt = 0; mt < 2; mt++) {
                const int r = wm * 32 + mt * 16 + g;
                af[mt][0] = __float_as_uint(As[r    ][ks * 8 + t    ]);
                af[mt][1] = __float_as_uint(As[r + 8][ks * 8 + t    ]);
                af[mt][2] = __float_as_uint(As[r    ][ks * 8 + t + 4]);
                af[mt][3] = __float_as_uint(As[r + 8][ks * 8 + t + 4]);
            }
#pragma unroll
            for (int nt = 0; nt < 4; nt++) {
                const int c = wn * 32 + nt * 8 + g;
                bf[nt][0] = __float_as_uint(Bs[c][ks * 8 + t    ]);
                bf[nt][1] = __float_as_uint(Bs[c][ks * 8 + t + 4]);
            }
#pragma unroll
            for (int mt = 0; mt < 2; mt++)
#pragma unroll
                for (int nt = 0; nt < 4; nt++)
                    mma_tf32(acc[mt][nt], af[mt], bf[nt]);
        }
    }

#pragma unroll
    for (int mt = 0; mt < 2; mt++) {
#pragma unroll
        for (int nt = 0; nt < 4; nt++) {
            const int row = bm + wm * 32 + mt * 16 + g;
            const int col = bn + wn * 32 + nt * 8 + 2 * t;
            const float2 bv = *(const float2*)(bias + col);
            float2 o0, o1;
            o0.x = acc[mt][nt][0] + bv.x;
            o0.y = acc[mt][nt][1] + bv.y;
            o1.x = acc[mt][nt][2] + bv.x;
            o1.y = acc[mt][nt][3] + bv.y;
            *(float2*)(C + (size_t)row * N + col)       = o0;
            *(float2*)(C + (size_t)(row + 8) * N + col) = o1;
        }
    }
}

// ---------------------------------------------------------------------------
// Flash-style attention, single pass over K/V:
//   per kt tile: S = Q@K^T (tf32 mma) -> raw S to global (from regs),
//   online m/Z, ctx rescale, P~ = exp(S - m) in regs, shuffle-convert to
//   A-fragments, ctx += P~@V. Final: ctx/Z -> g_ctx, (m,Z) -> stats.
// Weights get normalized in-place by a separate streaming kernel.
// ---------------------------------------------------------------------------
constexpr int AT_Q   = 64;     // q rows per block (4 warps x 16 rows)
constexpr int K_LD   = 68;     // Ks row stride: frag banks (4g+t) conflict-free
constexpr int V_LD   = 72;     // Vs row stride: frag banks (8t+g) conflict-free

__global__ __launch_bounds__(128, 4) void attention_flash_kernel(float* __restrict__ attn)
{
    __shared__ float Ks[64 * K_LD];
    __shared__ float Vs[64 * V_LD];

    const int tid  = threadIdx.x;
    const int lane = tid & 31;
    const int warp = tid >> 5;           // 0..3
    const int g    = lane >> 2;          // 0..7
    const int t    = lane & 3;           // 0..3

    const int qt = blockIdx.x;           // 0..31
    const int h  = blockIdx.y;
    const int b  = blockIdx.z;

    const float* Qg = g_q + (size_t)b * Sc * Dc + h * HDc;
    const float* Kg = g_k + (size_t)b * Sc * Dc + h * HDc;
    const float* Vg = g_v + (size_t)b * Sc * Dc + h * HDc;

    const int qrow = qt * AT_Q + warp * 16 + g;    // this thread's first q row

    // ---- Q fragments in registers, scaled by 1/8, tf32-rounded (one time) ----
    uint32_t qf[8][4];
#pragma unroll
    for (int ks = 0; ks < 8; ks++) {
        const float* q0 = Qg + (size_t)qrow * Dc + ks * 8;
        const float* q1 = Qg + (size_t)(qrow + 8) * Dc + ks * 8;
        qf[ks][0] = f2tf32(q0[t    ] * 0.125f);
        qf[ks][1] = f2tf32(q1[t    ] * 0.125f);
        qf[ks][2] = f2tf32(q0[t + 4] * 0.125f);
        qf[ks][3] = f2tf32(q1[t + 4] * 0.125f);
    }

    float ctx[8][4];
#pragma unroll
    for (int nt = 0; nt < 8; nt++)
#pragma unroll
        for (int i = 0; i < 4; i++) ctx[nt][i] = 0.f;

    float m0 = -INFINITY, m1 = -INFINITY, Z0 = 0.f, Z1 = 0.f;

    float* awr0 = attn + ((size_t)(b * Hc + h) * Sc + qrow) * Sc;
    float* awr1 = awr0 + (size_t)8 * Sc;

    for (int kt = 0; kt < Sc / 64; kt++) {
        // ---- load K and V tiles (coalesced float4), tf32-rounded ----
#pragma unroll
        for (int i = 0; i < 8; i++) {
            const int f  = tid + i * 128;
            const int r  = f >> 4;
            const int c4 = (f & 15) * 4;
            float4 kv = *(const float4*)(Kg + (size_t)(kt * 64 + r) * Dc + c4);
            Ks[r * K_LD + c4 + 0] = f2tf32f(kv.x);
            Ks[r * K_LD + c4 + 1] = f2tf32f(kv.y);
            Ks[r * K_LD + c4 + 2] = f2tf32f(kv.z);
            Ks[r * K_LD + c4 + 3] = f2tf32f(kv.w);
            float4 vv = *(const float4*)(Vg + (size_t)(kt * 64 + r) * Dc + c4);
            Vs[r * V_LD + c4 + 0] = f2tf32f(vv.x);
            Vs[r * V_LD + c4 + 1] = f2tf32f(vv.y);
            Vs[r * V_LD + c4 + 2] = f2tf32f(vv.z);
            Vs[r * V_LD + c4 + 3] = f2tf32f(vv.w);
        }
        __syncthreads();

        // ---- S = Q @ K^T ----
        float sacc[8][4];
#pragma unroll
        for (int nt = 0; nt < 8; nt++)
#pragma unroll
            for (int i = 0; i < 4; i++) sacc[nt][i] = 0.f;

#pragma unroll
        for (int ks = 0; ks < 8; ks++) {
#pragma unroll
            for (int nt = 0; nt < 8; nt++) {
                uint32_t bf[2];
                bf[0] = __float_as_uint(Ks[(nt * 8 + g) * K_LD + ks * 8 + t    ]);
                bf[1] = __float_as_uint(Ks[(nt * 8 + g) * K_LD + ks * 8 + t + 4]);
                mma_tf32(sacc[nt], qf[ks], bf);
            }
        }

        // ---- write raw scores straight from accumulators ----
#pragma unroll
        for (int nt = 0; nt < 8; nt++) {
            const int col = kt * 64 + nt * 8 + 2 * t;
            *(float2*)(awr0 + col) = make_float2(sacc[nt][0], sacc[nt][1]);
            *(float2*)(awr1 + col) = make_float2(sacc[nt][2], sacc[nt][3]);
        }

        // ---- online softmax stats ----
        float tm0 = -INFINITY, tm1 = -INFINITY;
#pragma unroll
        for (int nt = 0; nt < 8; nt++) {
            tm0 = fmaxf(tm0, fmaxf(sacc[nt][0], sacc[nt][1]));
            tm1 = fmaxf(tm1, fmaxf(sacc[nt][2], sacc[nt][3]));
        }
        tm0 = fmaxf(tm0, __shfl_xor_sync(0xffffffff, tm0, 1));
        tm0 = fmaxf(tm0, __shfl_xor_sync(0xffffffff, tm0, 2));
        tm1 = fmaxf(tm1, __shfl_xor_sync(0xffffffff, tm1, 1));
        tm1 = fmaxf(tm1, __shfl_xor_sync(0xffffffff, tm1, 2));

        const float m0n = fmaxf(m0, tm0);
        const float m1n = fmaxf(m1, tm1);
        const float sc0 = __expf(m0 - m0n);
        const float sc1 = __expf(m1 - m1n);

        float s0 = 0.f, s1 = 0.f;
#pragma unroll
        for (int nt = 0; nt < 8; nt++) {
            sacc[nt][0] = __expf(sacc[nt][0] - m0n);
            sacc[nt][1] = __expf(sacc[nt][1] - m0n);
            sacc[nt][2] = __expf(sacc[nt][2] - m1n);
            sacc[nt][3] = __expf(sacc[nt][3] - m1n);
            s0 += sacc[nt][0] + sacc[nt][1];
            s1 += sacc[nt][2] + sacc[nt][3];
        }
        s0 += __shfl_xor_sync(0xffffffff, s0, 1);
        s0 += __shfl_xor_sync(0xffffffff, s0, 2);
        s1 += __shfl_xor_sync(0xffffffff, s1, 1);
        s1 += __shfl_xor_sync(0xffffffff, s1, 2);

        Z0 = Z0 * sc0 + s0;  m0 = m0n;
        Z1 = Z1 * sc1 + s1;  m1 = m1n;

#pragma unroll
        for (int nt = 0; nt < 8; nt++) {
            ctx[nt][0] *= sc0;  ctx[nt][1] *= sc0;
            ctx[nt][2] *= sc1;  ctx[nt][3] *= sc1;
        }

        // ---- ctx += P~ @ V  (accumulator layout -> A fragment via shuffles) ----
        const int srcA = (lane & ~3) | (t >> 1);
        const bool odd = (t & 1);
#pragma unroll
        for (int j = 0; j < 8; j++) {
            const float e0 = __shfl_sync(0xffffffff, sacc[j][0], srcA);
            const float o0 = __shfl_sync(0xffffffff, sacc[j][1], srcA);
            const float e2 = __shfl_sync(0xffffffff, sacc[j][0], srcA + 2);
            const float o2 = __shfl_sync(0xffffffff, sacc[j][1], srcA + 2);
            const float e1 = __shfl_sync(0xffffffff, sacc[j][2], srcA);
            const float o1 = __shfl_sync(0xffffffff, sacc[j][3], srcA);
            const float e3 = __shfl_sync(0xffffffff, sacc[j][2], srcA + 2);
            const float o3 = __shfl_sync(0xffffffff, sacc[j][3], srcA + 2);
            uint32_t af[4];
            af[0] = f2tf32(odd ? o0 : e0);
            af[1] = f2tf32(odd ? o1 : e1);
            af[2] = f2tf32(odd ? o2 : e2);
            af[3] = f2tf32(odd ? o3 : e3);
#pragma unroll
            for (int nt = 0; nt < 8; nt++) {
                uint32_t bf[2];
                bf[0] = __float_as_uint(Vs[(j * 8 + t    ) * V_LD + nt * 8 + g]);
                bf[1] = __float_as_uint(Vs[(j * 8 + t + 4) * V_LD + nt * 8 + g]);
                mma_tf32(ctx[nt], af, bf);
            }
        }
        __syncthreads();   // before next tile overwrites Ks/Vs
    }

    // ---- epilogue: normalize ctx, write ctx + stats ----
    const float invZ0 = 1.0f / Z0;
    const float invZ1 = 1.0f / Z1;
    float* c0 = g_ctx + (size_t)(b * Sc + qrow) * Dc + h * HDc;
    float* c1 = c0 + (size_t)8 * Dc;
#pragma unroll
    for (int nt = 0; nt < 8; nt++) {
        const int col = nt * 8 + 2 * t;
        *(float2*)(c0 + col) = make_float2(ctx[nt][0] * invZ0, ctx[nt][1] * invZ0);
        *(float2*)(c1 + col) = make_float2(ctx[nt][2] * invZ1, ctx[nt][3] * invZ1);
    }
    if (t == 0) {
        const size_t sidx = (size_t)(b * Hc + h) * Sc + qrow;
        g_m[sidx]     = m0;  g_z[sidx]     = Z0;
        g_m[sidx + 8] = m1;  g_z[sidx + 8] = Z1;
    }
}

// ---------------------------------------------------------------------------
// Streaming normalize: w = exp(s - m_row) / Z_row, in place.
// One block per row (2048 floats), 256 threads, 2 float4 per thread.
// ---------------------------------------------------------------------------
__global__ __launch_bounds__(256) void normalize_kernel(float* __restrict__ attn)
{
    const int row = blockIdx.x;
    const float m    = g_m[row];
    const float invZ = 1.0f / g_z[row];
    float* p = attn + (size_t)row * Sc;
#pragma unroll
    for (int i = 0; i < 2; i++) {
        const int idx = (threadIdx.x + i * 256) * 4;
        float4 v = *(const float4*)(p + idx);
        v.x = __expf(v.x - m) * invZ;
        v.y = __expf(v.y - m) * invZ;
        v.z = __expf(v.z - m) * invZ;
        v.w = __expf(v.w - m) * invZ;
        *(float4*)(p + idx) = v;
    }
}

// ---------------------------------------------------------------------------
// kernel_launch
//   d_in: x, Wq, bq, Wk, bk, Wv, bv, Wo, bo   (all fp32)
//   d_out: [ out (B*S*D) | attention_weights (B*H*S*S) ]  fp32
// ---------------------------------------------------------------------------
extern "C" void kernel_launch(void* const* d_in, const int* in_sizes, int n_in,
                              void* d_out, int out_size)
{
    (void)in_sizes; (void)n_in; (void)out_size;
    const float* x  = (const float*)d_in[0];
    const float* Wq = (const float*)d_in[1];
    const float* bq = (const float*)d_in[2];
    const float* Wk = (const float*)d_in[3];
    const float* bk = (const float*)d_in[4];
    const float* Wv = (const float*)d_in[5];
    const float* bv = (const float*)d_in[6];
    const float* Wo = (const float*)d_in[7];
    const float* bo = (const float*)d_in[8];

    float* out  = (float*)d_out;
    float* attn = out + (size_t)Bc * Sc * Dc;

    float* gq;  cudaGetSymbolAddress((void**)&gq,  g_q);
    float* gk;  cudaGetSymbolAddress((void**)&gk,  g_k);
    float* gv;  cudaGetSymbolAddress((void**)&gv,  g_v);
    float* gc;  cudaGetSymbolAddress((void**)&gc,  g_ctx);

    dim3 gemmBlock(256);

    // Q/K/V projections fused into one launch
    dim3 qkvGrid(Dc / 64, Mc / 128, 3);      // (16, 32, 3)
    gemm3_tf32_nt_bias<<<qkvGrid, gemmBlock>>>(
        x, Wq, bq, gq, Wk, bk, gk, Wv, bv, gv, Mc, Dc, Dc);

    // Flash attention: raw scores + stats + ctx
    dim3 attnGrid(Sc / AT_Q, Hc, Bc);        // (32, 16, 2)
    attention_flash_kernel<<<attnGrid, 128>>>(attn);

    // Normalize weights in place (one block per row)
    normalize_kernel<<<Bc * Hc * Sc, 256>>>(attn);

    // Output projection (single problem: route all three slots to it)
    dim3 oGrid(Dc / 64, Mc / 128, 1);        // (16, 32, 1)
    gemm3_tf32_nt_bias<<<oGrid, gemmBlock>>>(
        gc, Wo, bo, out, Wo, bo, out, Wo, bo, out, Mc, Dc, Dc);
}